// round 12
// baseline (speedup 1.0000x reference)
#include <cuda_runtime.h>
#include <cuda_bf16.h>
#include <cstdint>
#include <math.h>

#define NN 50000
#define EE 625000
#define DD 128
#define MEPS 1e-7f
#define BSTRIDE 64
#define NRB16 3125            // 16-row fragment blocks: 50000 = 3125*16 exactly
#define NRBALLOC 3136

#define ATS   136             // bf16 elements per smem row (128 + 8 pad)
#define ATS_B 272             // row stride bytes
#define BTILE (128 * ATS_B)   // 34816 B per [128][136] bf16 tile

// ---- k_mma dynamic smem byte offsets (B + params only) ----------------------
#define SM_BHI  0
#define SM_BLO  (SM_BHI + BTILE)             // 34816
#define SM_BIAS (SM_BLO + BTILE)             // 69632
#define SM_GAM  (SM_BIAS + 512)
#define SM_BET  (SM_GAM + 512)
#define SM_TOTAL (SM_BET + 512)              // 71168 B -> 2 CTAs/SM (smem), 16 warps

// ================= device scratch =============================================
__device__ __align__(16) float g_h [NN * DD];            // residual state / layer-0 input
__device__ __align__(16) float g_h2[NN * DD];            // relu(LN(h)) next conv input
__device__ __align__(16) uint32_t g_Afh[NRBALLOC * 1024];// A hi, m16n8k16 fragment layout
__device__ __align__(16) uint32_t g_Afl[NRBALLOC * 1024];// A lo
__device__ __align__(16) float g_pair[64 * DD];          // (a0,a1) bond table
__device__ __align__(16) float g_b2  [8 * DD];           // bond feature-2 table
__device__ int g_cursor[NN];
__device__ int g_packed[NN * BSTRIDE];                   // src(16b)|a0<<16|a1<<19|a2<<22

// ================= helpers ====================================================
__device__ __forceinline__ uint32_t smem_to_u32(const void* smem_ptr) {
    uint32_t addr;
    asm("{ .reg .u64 tmp; cvta.to.shared.u64 tmp, %1; cvt.u32.u64 %0, tmp; }"
        : "=r"(addr) : "l"(smem_ptr));
    return addr;
}

__device__ __forceinline__ void ldsm4(uint32_t& r0, uint32_t& r1, uint32_t& r2,
                                      uint32_t& r3, uint32_t addr) {
    asm volatile("ldmatrix.sync.aligned.m8n8.x4.shared.b16 {%0,%1,%2,%3}, [%4];"
                 : "=r"(r0), "=r"(r1), "=r"(r2), "=r"(r3) : "r"(addr));
}

__device__ __forceinline__ void mma_bf16(float& d0, float& d1, float& d2, float& d3,
                                         uint32_t a0, uint32_t a1, uint32_t a2, uint32_t a3,
                                         uint32_t b0, uint32_t b1) {
    asm volatile("mma.sync.aligned.m16n8k16.row.col.f32.bf16.bf16.f32 "
                 "{%0,%1,%2,%3}, {%4,%5,%6,%7}, {%8,%9}, {%0,%1,%2,%3};"
                 : "+f"(d0), "+f"(d1), "+f"(d2), "+f"(d3)
                 : "r"(a0), "r"(a1), "r"(a2), "r"(a3), "r"(b0), "r"(b1));
}

__device__ __forceinline__ unsigned long long f2u(float2 v) {
    return *reinterpret_cast<unsigned long long*>(&v);
}
__device__ __forceinline__ float2 u2f2(unsigned long long v) {
    return *reinterpret_cast<float2*>(&v);
}
__device__ __forceinline__ float2 f2add(float2 a, float2 b) {
    unsigned long long d;
    asm("add.rn.f32x2 %0,%1,%2;" : "=l"(d) : "l"(f2u(a)), "l"(f2u(b)));
    return u2f2(d);
}
__device__ __forceinline__ float2 f2mul(float2 a, float2 b) {
    unsigned long long d;
    asm("mul.rn.f32x2 %0,%1,%2;" : "=l"(d) : "l"(f2u(a)), "l"(f2u(b)));
    return u2f2(d);
}
__device__ __forceinline__ float2 f2fma(float2 a, float2 b, float2 c) {
    unsigned long long d;
    asm("fma.rn.f32x2 %0,%1,%2,%3;" : "=l"(d) : "l"(f2u(a)), "l"(f2u(b)), "l"(f2u(c)));
    return u2f2(d);
}

__device__ __forceinline__ unsigned pack2(__nv_bfloat16 a, __nv_bfloat16 b) {
    __nv_bfloat162 t = __halves2bfloat162(a, b);
    return *reinterpret_cast<unsigned*>(&t);
}
__device__ __forceinline__ void bsplit(float v, __nv_bfloat16& hi, __nv_bfloat16& lo) {
    hi = __float2bfloat16(v);
    lo = __float2bfloat16(v - __bfloat162float(hi));
}

// ================= prep =======================================================
__global__ void k_atom(const int* __restrict__ x, const float* __restrict__ aemb,
                       const float* __restrict__ bemb) {
    int i = blockIdx.x * blockDim.x + threadIdx.x;   // NN*32 float4 slots
    if (i >= NN * 32) return;
    int n = i >> 5, q = i & 31;
    if (q == 0) g_cursor[n] = 0;
    if (i < 64 * 32) {                               // pair table: c = a0 | a1<<3
        int c = i >> 5, qq = i & 31;
        float4 u = ((const float4*)(bemb + ((c & 7)     ) * DD))[qq];
        float4 v = ((const float4*)(bemb + (8 + (c >> 3)) * DD))[qq];
        ((float4*)(g_pair + c * DD))[qq] =
            make_float4(u.x + v.x, u.y + v.y, u.z + v.z, u.w + v.w);
    }
    if (i < 8 * 32)
        ((float4*)g_b2)[i] = ((const float4*)(bemb + 16 * DD))[i];
    float4 s = make_float4(0.f, 0.f, 0.f, 0.f);
#pragma unroll
    for (int f = 0; f < 9; ++f) {
        int v = x[n * 9 + f];
        float4 t = ((const float4*)(aemb + (f * 64 + v) * DD))[q];
        s.x += t.x; s.y += t.y; s.z += t.z; s.w += t.w;
    }
    ((float4*)(g_h + n * DD))[q] = s;
}

__global__ void k_scatter(const int* __restrict__ src, const int* __restrict__ dst,
                          const int* __restrict__ ea) {
    int e = blockIdx.x * blockDim.x + threadIdx.x;
    if (e >= EE) return;
    int d = dst[e];
    int pos = atomicAdd(&g_cursor[d], 1);
    if (pos < BSTRIDE) {
        int p = src[e] | (ea[e * 3] << 16) | (ea[e * 3 + 1] << 19) | (ea[e * 3 + 2] << 22);
        g_packed[d * BSTRIDE + pos] = p;
    }
}

// ================= aggregation (persistent; writes fragment-layout A) =========
// (verbatim R10 — correctness proven at rel_err 6.0e-6)
__global__ void __launch_bounds__(256, 5) k_agg(const float* __restrict__ hin) {
    __shared__ float SP[64 * DD];
    __shared__ float S2[8 * DD];
    int tid = threadIdx.x;
    for (int i = tid; i < 64 * 32; i += 256) ((float4*)SP)[i] = ((const float4*)g_pair)[i];
    if (tid < 8 * 32) ((float4*)S2)[tid] = ((const float4*)g_b2)[tid];
    __syncthreads();

    int warp = tid >> 5, lane = tid & 31;
    const float4* SPl = (const float4*)SP + lane;
    const float4* S2l = (const float4*)S2 + lane;
    const float4* Hl  = (const float4*)hin + lane;
    const float2 l2e = make_float2(1.4426950408889634f, 1.4426950408889634f);

    for (int n = blockIdx.x * 8 + warp; n < NN; n += gridDim.x * 8) {
        int deg = g_cursor[n]; if (deg > BSTRIDE) deg = BSTRIDE;
        int base = n * BSTRIDE;
        int pk0 = g_packed[base + lane];
        int pk1 = g_packed[base + 32 + lane];

        float2 den01 = make_float2(0.f, 0.f), den23 = make_float2(0.f, 0.f);
        float2 num01 = make_float2(0.f, 0.f), num23 = make_float2(0.f, 0.f);

        auto proc = [&](int p) {
            const float4 hv = __ldg(Hl + (p & 0xFFFF) * 32);
            const float4 c  = SPl[((p >> 16) & 63) * 32];
            const float4 d  = S2l[((p >> 22) & 7) * 32];
            float2 t01 = f2add(make_float2(hv.x, hv.y), make_float2(c.x, c.y));
            float2 t23 = f2add(make_float2(hv.z, hv.w), make_float2(c.z, c.w));
            t01 = f2add(t01, make_float2(d.x, d.y));
            t23 = f2add(t23, make_float2(d.z, d.w));
            float2 m01 = make_float2(fmaxf(t01.x, 0.f), fmaxf(t01.y, 0.f));
            float2 m23 = make_float2(fmaxf(t23.x, 0.f), fmaxf(t23.y, 0.f));
            float2 x01 = f2mul(m01, l2e);
            float2 x23 = f2mul(m23, l2e);
            float2 e01 = make_float2(exp2f(x01.x), exp2f(x01.y));
            float2 e23 = make_float2(exp2f(x23.x), exp2f(x23.y));
            den01 = f2add(den01, e01);  den23 = f2add(den23, e23);
            num01 = f2fma(e01, m01, num01);  num23 = f2fma(e23, m23, num23);
        };

        int pairs = deg & ~1;
        for (int i = 0; i < pairs; i += 2) {
            int p0 = __shfl_sync(0xffffffffu, (i < 32) ? pk0 : pk1, i & 31);
            int j = i + 1;
            int p1 = __shfl_sync(0xffffffffu, (j < 32) ? pk0 : pk1, j & 31);
            proc(p0);
            proc(p1);
        }
        if (deg & 1) {
            int p = __shfl_sync(0xffffffffu, (pairs < 32) ? pk0 : pk1, pairs & 31);
            proc(p);
        }

        float4 hn = __ldg(Hl + n * 32);
        float4 o;
        o.x = hn.x + num01.x / (den01.x + 1e-16f) + MEPS;
        o.y = hn.y + num01.y / (den01.y + 1e-16f) + MEPS;
        o.z = hn.z + num23.x / (den23.x + 1e-16f) + MEPS;
        o.w = hn.w + num23.y / (den23.y + 1e-16f) + MEPS;

        __nv_bfloat16 h0, h1, h2, h3, l0, l1, l2, l3;
        bsplit(o.x, h0, l0); bsplit(o.y, h1, l1);
        bsplit(o.z, h2, l2); bsplit(o.w, h3, l3);
        uint32_t uh0 = pack2(h0, h1), uh1 = pack2(h2, h3);
        uint32_t ul0 = pack2(l0, l1), ul1 = pack2(l2, l3);

        // scatter into m16n8k16 fragment layout: word j covers cols 2j, 2j+1
        int rb = n >> 4, rr = n & 15;
        int rbase = rb * 1024;
        int rlo = (rr & 7) * 4;
        int rhi = rr >> 3;
        {
            int j = 2 * lane;
            int ks = j >> 3, jj = j & 7;
            int addr = rbase + ks * 128 + (rlo + (jj & 3)) * 4 + rhi + 2 * (jj >> 2);
            g_Afh[addr] = uh0;
            g_Afl[addr] = ul0;
        }
        {
            int j = 2 * lane + 1;
            int ks = j >> 3, jj = j & 7;
            int addr = rbase + ks * 128 + (rlo + (jj & 3)) * 4 + rhi + 2 * (jj >> 2);
            g_Afh[addr] = uh1;
            g_Afl[addr] = ul1;
        }
    }
}

// ================= HMMA GEMM: warp owns 16 rows x 128 cols, no loop barriers ==
template <bool RES, bool FINAL>
__global__ void __launch_bounds__(256, 2) k_mma(const float* __restrict__ Wl,
                                                const float* __restrict__ bl,
                                                const float* __restrict__ gl,
                                                const float* __restrict__ btl,
                                                float* __restrict__ dout) {
    extern __shared__ char smc[];
    uint32_t sb = smem_to_u32(smc);
    int tid = threadIdx.x;
    int warp = tid >> 5, lane = tid & 31;

    // ---- prologue: W transpose+split into B[n][k] hi/lo, bias/gamma/beta ----
    for (int i = tid; i < 128 * 32; i += 256) {
        int k = i >> 5, q = i & 31;
        float4 w = *(const float4*)&Wl[k * DD + q * 4];
#pragma unroll
        for (int e = 0; e < 4; ++e) {
            int n = q * 4 + e;
            float val = (e == 0) ? w.x : (e == 1) ? w.y : (e == 2) ? w.z : w.w;
            __nv_bfloat16 hi, lo;
            bsplit(val, hi, lo);
            ((__nv_bfloat16*)(smc + SM_BHI))[n * ATS + k] = hi;
            ((__nv_bfloat16*)(smc + SM_BLO))[n * ATS + k] = lo;
        }
    }
    for (int i = tid; i < 128; i += 256) {
        ((float*)(smc + SM_BIAS))[i] = bl[i];
        ((float*)(smc + SM_GAM))[i]  = gl[i];
        ((float*)(smc + SM_BET))[i]  = btl[i];
    }
    __syncthreads();

    // B ldmatrix per-lane offset (proven R9 mapping); warp covers ALL 128 cols
    uint32_t b_loff = (uint32_t)((((lane & 7) + ((lane >> 4) & 1) * 8) * ATS
                                  + ((lane >> 3) & 1) * 8) * 2);
    uint32_t bhi_base = sb + SM_BHI + b_loff;
    uint32_t blo_base = sb + SM_BLO + b_loff;

    const float* bias = (const float*)(smc + SM_BIAS);
    const float* gam  = (const float*)(smc + SM_GAM);
    const float* bet  = (const float*)(smc + SM_BET);
    const uint4* A4h  = (const uint4*)g_Afh;    // 256 uint4 per 16-row block
    const uint4* A4l  = (const uint4*)g_Afl;

    int l23 = lane >> 2;            // 0-7
    int lc  = (lane & 3) * 2;
    int gw  = blockIdx.x * 8 + warp;
    int nwt = gridDim.x * 8;

    for (int rb = gw; rb < NRB16; rb += nwt) {
        float acc[16][4];
#pragma unroll
        for (int nt = 0; nt < 16; ++nt)
#pragma unroll
            for (int e = 0; e < 4; ++e) acc[nt][e] = 0.f;

#pragma unroll
        for (int ks = 0; ks < 8; ++ks) {
            uint4 Ah = A4h[rb * 256 + ks * 32 + lane];
            uint4 Al = A4l[rb * 256 + ks * 32 + lane];
            uint32_t kofs = (uint32_t)(ks * 32);
#pragma unroll
            for (int ntp = 0; ntp < 8; ++ntp) {
                uint32_t boff = (uint32_t)(ntp * 16 * ATS_B) + kofs;
                uint32_t bh0, bh1, bh2, bh3, bl0, bl1, bl2, bl3;
                ldsm4(bh0, bh1, bh2, bh3, bhi_base + boff);
                ldsm4(bl0, bl1, bl2, bl3, blo_base + boff);
                int n0 = 2 * ntp, n1 = 2 * ntp + 1;
                mma_bf16(acc[n0][0], acc[n0][1], acc[n0][2], acc[n0][3],
                         Ah.x, Ah.y, Ah.z, Ah.w, bh0, bh1);
                mma_bf16(acc[n0][0], acc[n0][1], acc[n0][2], acc[n0][3],
                         Ah.x, Ah.y, Ah.z, Ah.w, bl0, bl1);
                mma_bf16(acc[n0][0], acc[n0][1], acc[n0][2], acc[n0][3],
                         Al.x, Al.y, Al.z, Al.w, bh0, bh1);
                mma_bf16(acc[n1][0], acc[n1][1], acc[n1][2], acc[n1][3],
                         Ah.x, Ah.y, Ah.z, Ah.w, bh2, bh3);
                mma_bf16(acc[n1][0], acc[n1][1], acc[n1][2], acc[n1][3],
                         Ah.x, Ah.y, Ah.z, Ah.w, bl2, bl3);
                mma_bf16(acc[n1][0], acc[n1][1], acc[n1][2], acc[n1][3],
                         Al.x, Al.y, Al.z, Al.w, bh2, bh3);
            }
        }

        // ---- warp-local epilogue: bias (+residual), LN (4-lane shfl), store --
        int r0 = rb * 16 + l23;        // rows all < NN (50000 = 3125*16)
        int r1 = r0 + 8;
        float s0 = 0.f, q0 = 0.f, s1 = 0.f, q1 = 0.f;
#pragma unroll
        for (int nt = 0; nt < 16; ++nt) {
            int c = nt * 8 + lc;
            float2 bv = *(const float2*)(bias + c);
            float v0 = acc[nt][0] + bv.x;
            float v1 = acc[nt][1] + bv.y;
            float v2 = acc[nt][2] + bv.x;
            float v3 = acc[nt][3] + bv.y;
            if (RES) {
                float2 rv0 = *(const float2*)&g_h[r0 * DD + c];
                float2 rv1 = *(const float2*)&g_h[r1 * DD + c];
                v0 += rv0.x; v1 += rv0.y; v2 += rv1.x; v3 += rv1.y;
            }
            acc[nt][0] = v0; acc[nt][1] = v1; acc[nt][2] = v2; acc[nt][3] = v3;
            s0 += v0 + v1; q0 += v0 * v0 + v1 * v1;
            s1 += v2 + v3; q1 += v2 * v2 + v3 * v3;
        }
        s0 += __shfl_xor_sync(0xffffffffu, s0, 1); s0 += __shfl_xor_sync(0xffffffffu, s0, 2);
        q0 += __shfl_xor_sync(0xffffffffu, q0, 1); q0 += __shfl_xor_sync(0xffffffffu, q0, 2);
        s1 += __shfl_xor_sync(0xffffffffu, s1, 1); s1 += __shfl_xor_sync(0xffffffffu, s1, 2);
        q1 += __shfl_xor_sync(0xffffffffu, q1, 1); q1 += __shfl_xor_sync(0xffffffffu, q1, 2);
        float mu0 = s0 * (1.f / 128.f), mu1 = s1 * (1.f / 128.f);
        float rs0 = rsqrtf(q0 * (1.f / 128.f) - mu0 * mu0 + 1e-5f);
        float rs1 = rsqrtf(q1 * (1.f / 128.f) - mu1 * mu1 + 1e-5f);

#pragma unroll
        for (int nt = 0; nt < 16; ++nt) {
            int c = nt * 8 + lc;
            float2 gv = *(const float2*)(gam + c);
            float2 tv = *(const float2*)(bet + c);
            float v0 = acc[nt][0], v1 = acc[nt][1];
            float v2 = acc[nt][2], v3 = acc[nt][3];
            float y0 = (v0 - mu0) * rs0 * gv.x + tv.x;
            float y1 = (v1 - mu0) * rs0 * gv.y + tv.y;
            float y2 = (v2 - mu1) * rs1 * gv.x + tv.x;
            float y3 = (v3 - mu1) * rs1 * gv.y + tv.y;
            if (FINAL) {
                *(float2*)&dout[r0 * DD + c] = make_float2(y0, y1);
                *(float2*)&dout[r1 * DD + c] = make_float2(y2, y3);
            } else {
                *(float2*)&g_h [r0 * DD + c] = make_float2(v0, v1);
                *(float2*)&g_h [r1 * DD + c] = make_float2(v2, v3);
                *(float2*)&g_h2[r0 * DD + c] = make_float2(fmaxf(y0, 0.f), fmaxf(y1, 0.f));
                *(float2*)&g_h2[r1 * DD + c] = make_float2(fmaxf(y2, 0.f), fmaxf(y3, 0.f));
            }
        }
    }
}

// ================= launch =====================================================
extern "C" void kernel_launch(void* const* d_in, const int* in_sizes, int n_in,
                              void* d_out, int out_size) {
    const int*   x    = (const int*)  d_in[0];
    const int*   ei   = (const int*)  d_in[1];
    const int*   ea   = (const int*)  d_in[2];
    const float* aemb = (const float*)d_in[3];
    const float* bemb = (const float*)d_in[4];
    const float* W    = (const float*)d_in[5];
    const float* b    = (const float*)d_in[6];
    const float* g    = (const float*)d_in[7];
    const float* bt   = (const float*)d_in[8];
    float* out = (float*)d_out;
    const int* src = ei;
    const int* dst = ei + EE;

    static float *p_h = nullptr, *p_h2 = nullptr;
    static int sms = 148;
    if (!p_h) {
        cudaGetSymbolAddress((void**)&p_h,  g_h);
        cudaGetSymbolAddress((void**)&p_h2, g_h2);
        cudaDeviceGetAttribute(&sms, cudaDevAttrMultiProcessorCount, 0);
        cudaFuncSetAttribute((const void*)k_mma<false, false>, cudaFuncAttributeMaxDynamicSharedMemorySize, SM_TOTAL);
        cudaFuncSetAttribute((const void*)k_mma<true,  false>, cudaFuncAttributeMaxDynamicSharedMemorySize, SM_TOTAL);
        cudaFuncSetAttribute((const void*)k_mma<true,  true >, cudaFuncAttributeMaxDynamicSharedMemorySize, SM_TOTAL);
    }

    k_atom<<<(NN * 32 + 255) / 256, 256>>>(x, aemb, bemb);     // launch 0
    k_scatter<<<(EE + 255) / 256, 256>>>(src, dst, ea);        // launch 1

    int agg_blocks = sms * 5;
    int mma_blocks = sms * 2;
    for (int l = 0; l < 7; ++l) {
        const float* Wl  = W  + l * DD * DD;
        const float* bl  = b  + l * DD;
        const float* gl  = g  + l * DD;
        const float* btl = bt + l * DD;
        const float* hi = (l == 0) ? p_h : p_h2;
        k_agg<<<agg_blocks, 256>>>(hi);                        // launch 2 = agg0
        if (l == 0)
            k_mma<false, false><<<mma_blocks, 256, SM_TOTAL>>>(Wl, bl, gl, btl, out);  // launch 3 (profiled)
        else if (l < 6)
            k_mma<true, false><<<mma_blocks, 256, SM_TOTAL>>>(Wl, bl, gl, btl, out);
        else
            k_mma<true, true><<<mma_blocks, 256, SM_TOTAL>>>(Wl, bl, gl, btl, out);
    }
}

// round 13
// speedup vs baseline: 1.0639x; 1.0639x over previous
#include <cuda_runtime.h>
#include <cuda_bf16.h>
#include <cuda_pipeline_primitives.h>
#include <cstdint>
#include <math.h>

#define NN 50000
#define EE 625000
#define DD 128
#define MEPS 1e-7f
#define BSTRIDE 64
#define NTILES 391            // ceil(NN/128)
#define L2E 1.4426950408889634f
#define INV_L2E 0.6931471805599453f

#define ATS   136             // bf16 elements per smem row (128 + 8 pad)
#define ATS_B 272             // row stride bytes

// ---- k_mma dynamic smem byte offsets (R9 layout) ----------------------------
#define SM_BHI  0
#define SM_BLO  (SM_BHI + 128 * ATS_B)       // 34816
#define SM_A    (SM_BLO + 128 * ATS_B)       // 69632: buf0 hi, buf0 lo, buf1 hi, buf1 lo
#define SM_BIAS (SM_A + 4 * 128 * ATS_B)     // 208896
#define SM_GAM  (SM_BIAS + 512)
#define SM_BET  (SM_GAM + 512)
#define SM_LNP  (SM_BET + 512)               // 128 rows x 4 warps x float2 = 4096
#define SM_TOTAL (SM_LNP + 4096)             // 214528 B

// ================= device scratch =============================================
__device__ __align__(16) float g_h [NN * DD];            // residual state (true scale)
__device__ __align__(16) float g_hs[NN * DD];            // h * log2e (layer-0 agg input)
__device__ __align__(16) float g_h2[NN * DD];            // relu(LN(h)) * log2e (agg input l>=1)
__device__ __align__(16) __nv_bfloat16 g_Ahi[NN * DD];   // agg output hi (GEMM A)
__device__ __align__(16) __nv_bfloat16 g_Alo[NN * DD];   // agg output lo
__device__ __align__(16) float g_pair[64 * DD];          // (a0,a1) bond table (true scale)
__device__ __align__(16) float g_b2  [8 * DD];           // bond feature-2 table
__device__ int g_cursor[NN];
__device__ int g_packed[NN * BSTRIDE];                   // src(16b)|a0<<16|a1<<19|a2<<22

// ================= helpers ====================================================
__device__ __forceinline__ uint32_t smem_to_u32(const void* smem_ptr) {
    uint32_t addr;
    asm("{ .reg .u64 tmp; cvta.to.shared.u64 tmp, %1; cvt.u32.u64 %0, tmp; }"
        : "=r"(addr) : "l"(smem_ptr));
    return addr;
}

__device__ __forceinline__ void ldsm4(uint32_t& r0, uint32_t& r1, uint32_t& r2,
                                      uint32_t& r3, uint32_t addr) {
    asm volatile("ldmatrix.sync.aligned.m8n8.x4.shared.b16 {%0,%1,%2,%3}, [%4];"
                 : "=r"(r0), "=r"(r1), "=r"(r2), "=r"(r3) : "r"(addr));
}

__device__ __forceinline__ void mma_bf16(float& d0, float& d1, float& d2, float& d3,
                                         uint32_t a0, uint32_t a1, uint32_t a2, uint32_t a3,
                                         uint32_t b0, uint32_t b1) {
    asm volatile("mma.sync.aligned.m16n8k16.row.col.f32.bf16.bf16.f32 "
                 "{%0,%1,%2,%3}, {%4,%5,%6,%7}, {%8,%9}, {%0,%1,%2,%3};"
                 : "+f"(d0), "+f"(d1), "+f"(d2), "+f"(d3)
                 : "r"(a0), "r"(a1), "r"(a2), "r"(a3), "r"(b0), "r"(b1));
}

__device__ __forceinline__ unsigned long long f2u(float2 v) {
    return *reinterpret_cast<unsigned long long*>(&v);
}
__device__ __forceinline__ float2 u2f2(unsigned long long v) {
    return *reinterpret_cast<float2*>(&v);
}
__device__ __forceinline__ float2 f2add(float2 a, float2 b) {
    unsigned long long d;
    asm("add.rn.f32x2 %0,%1,%2;" : "=l"(d) : "l"(f2u(a)), "l"(f2u(b)));
    return u2f2(d);
}
__device__ __forceinline__ float2 f2fma(float2 a, float2 b, float2 c) {
    unsigned long long d;
    asm("fma.rn.f32x2 %0,%1,%2,%3;" : "=l"(d) : "l"(f2u(a)), "l"(f2u(b)), "l"(f2u(c)));
    return u2f2(d);
}

__device__ __forceinline__ unsigned pack2(__nv_bfloat16 a, __nv_bfloat16 b) {
    __nv_bfloat162 t = __halves2bfloat162(a, b);
    return *reinterpret_cast<unsigned*>(&t);
}
__device__ __forceinline__ void bsplit(float v, __nv_bfloat16& hi, __nv_bfloat16& lo) {
    hi = __float2bfloat16(v);
    lo = __float2bfloat16(v - __bfloat162float(hi));
}

// ================= prep =======================================================
__global__ void k_atom(const int* __restrict__ x, const float* __restrict__ aemb,
                       const float* __restrict__ bemb) {
    int i = blockIdx.x * blockDim.x + threadIdx.x;   // NN*32 float4 slots
    if (i >= NN * 32) return;
    int n = i >> 5, q = i & 31;
    if (q == 0) g_cursor[n] = 0;
    if (i < 64 * 32) {                               // pair table: c = a0 | a1<<3
        int c = i >> 5, qq = i & 31;
        float4 u = ((const float4*)(bemb + ((c & 7)     ) * DD))[qq];
        float4 v = ((const float4*)(bemb + (8 + (c >> 3)) * DD))[qq];
        ((float4*)(g_pair + c * DD))[qq] =
            make_float4(u.x + v.x, u.y + v.y, u.z + v.z, u.w + v.w);
    }
    if (i < 8 * 32)
        ((float4*)g_b2)[i] = ((const float4*)(bemb + 16 * DD))[i];
    float4 s = make_float4(0.f, 0.f, 0.f, 0.f);
#pragma unroll
    for (int f = 0; f < 9; ++f) {
        int v = x[n * 9 + f];
        float4 t = ((const float4*)(aemb + (f * 64 + v) * DD))[q];
        s.x += t.x; s.y += t.y; s.z += t.z; s.w += t.w;
    }
    ((float4*)(g_h + n * DD))[q] = s;
    ((float4*)(g_hs + n * DD))[q] =
        make_float4(s.x * L2E, s.y * L2E, s.z * L2E, s.w * L2E);
}

__global__ void k_scatter(const int* __restrict__ src, const int* __restrict__ dst,
                          const int* __restrict__ ea) {
    int e = blockIdx.x * blockDim.x + threadIdx.x;
    if (e >= EE) return;
    int d = dst[e];
    int pos = atomicAdd(&g_cursor[d], 1);
    if (pos < BSTRIDE) {
        int p = src[e] | (ea[e * 3] << 16) | (ea[e * 3 + 1] << 19) | (ea[e * 3 + 2] << 22);
        g_packed[d * BSTRIDE + pos] = p;
    }
}

// ================= aggregation (persistent; log2-domain inputs) ===============
// hin is PRE-SCALED by log2e. Tables scaled at smem load. Per edge: sum, relu,
// exp2 direct. Per node: one unscale multiply. Exp(eps) factor cancels (exact).
__global__ void __launch_bounds__(256, 5) k_agg(const float* __restrict__ hin) {
    __shared__ float SP[64 * DD];
    __shared__ float S2[8 * DD];
    int tid = threadIdx.x;
    for (int i = tid; i < 64 * 32; i += 256) {
        float4 v = ((const float4*)g_pair)[i];
        ((float4*)SP)[i] = make_float4(v.x * L2E, v.y * L2E, v.z * L2E, v.w * L2E);
    }
    if (tid < 8 * 32) {
        float4 v = ((const float4*)g_b2)[tid];
        ((float4*)S2)[tid] = make_float4(v.x * L2E, v.y * L2E, v.z * L2E, v.w * L2E);
    }
    __syncthreads();

    int warp = tid >> 5, lane = tid & 31;
    const float4* SPl = (const float4*)SP + lane;
    const float4* S2l = (const float4*)S2 + lane;
    const float4* Hl  = (const float4*)hin + lane;

    for (int n = blockIdx.x * 8 + warp; n < NN; n += gridDim.x * 8) {
        int deg = g_cursor[n]; if (deg > BSTRIDE) deg = BSTRIDE;
        int base = n * BSTRIDE;
        int pk0 = g_packed[base + lane];
        int pk1 = g_packed[base + 32 + lane];

        float2 den01 = make_float2(0.f, 0.f), den23 = make_float2(0.f, 0.f);
        float2 num01 = make_float2(0.f, 0.f), num23 = make_float2(0.f, 0.f);

        auto proc = [&](int p) {
            const float4 hv = __ldg(Hl + (p & 0xFFFF) * 32);
            const float4 c  = SPl[((p >> 16) & 63) * 32];
            const float4 d  = S2l[((p >> 22) & 7) * 32];
            float2 t01 = f2add(make_float2(hv.x, hv.y), make_float2(c.x, c.y));
            float2 t23 = f2add(make_float2(hv.z, hv.w), make_float2(c.z, c.w));
            t01 = f2add(t01, make_float2(d.x, d.y));
            t23 = f2add(t23, make_float2(d.z, d.w));
            float2 m01 = make_float2(fmaxf(t01.x, 0.f), fmaxf(t01.y, 0.f));
            float2 m23 = make_float2(fmaxf(t23.x, 0.f), fmaxf(t23.y, 0.f));
            float2 e01 = make_float2(exp2f(m01.x), exp2f(m01.y));
            float2 e23 = make_float2(exp2f(m23.x), exp2f(m23.y));
            den01 = f2add(den01, e01);  den23 = f2add(den23, e23);
            num01 = f2fma(e01, m01, num01);  num23 = f2fma(e23, m23, num23);
        };

        int pairs = deg & ~1;
        for (int i = 0; i < pairs; i += 2) {
            int p0 = __shfl_sync(0xffffffffu, (i < 32) ? pk0 : pk1, i & 31);
            int j = i + 1;
            int p1 = __shfl_sync(0xffffffffu, (j < 32) ? pk0 : pk1, j & 31);
            proc(p0);
            proc(p1);
        }
        if (deg & 1) {
            int p = __shfl_sync(0xffffffffu, (pairs < 32) ? pk0 : pk1, pairs & 31);
            proc(p);
        }

        float4 hn = __ldg(Hl + n * 32);      // scaled self row
        float4 o;
        o.x = (hn.x + num01.x / (den01.x + 1e-16f)) * INV_L2E + MEPS;
        o.y = (hn.y + num01.y / (den01.y + 1e-16f)) * INV_L2E + MEPS;
        o.z = (hn.z + num23.x / (den23.x + 1e-16f)) * INV_L2E + MEPS;
        o.w = (hn.w + num23.y / (den23.y + 1e-16f)) * INV_L2E + MEPS;

        __nv_bfloat16 h0, h1, h2, h3, l0, l1, l2, l3;
        bsplit(o.x, h0, l0); bsplit(o.y, h1, l1);
        bsplit(o.z, h2, l2); bsplit(o.w, h3, l3);
        uint2 uh, ul;
        uh.x = pack2(h0, h1); uh.y = pack2(h2, h3);
        ul.x = pack2(l0, l1); ul.y = pack2(l2, l3);
        ((uint2*)(g_Ahi + n * DD))[lane] = uh;
        ((uint2*)(g_Alo + n * DD))[lane] = ul;
    }
}

// ================= HMMA GEMM layer (R9 champion, verbatim + gamma scaling) ====
template <bool RES, bool FINAL>
__global__ void __launch_bounds__(512, 1) k_mma(const float* __restrict__ Wl,
                                                const float* __restrict__ bl,
                                                const float* __restrict__ gl,
                                                const float* __restrict__ btl,
                                                float* __restrict__ dout) {
    extern __shared__ char smc[];
    uint32_t sb = smem_to_u32(smc);
    int tid = threadIdx.x;
    int warp = tid >> 5, lane = tid & 31;
    int wm = warp >> 2, wn = warp & 3;      // 4x4 warp grid: 32-row x 32-col warp tiles

    // ---- prologue: W transpose+split into B[n][k], bias/gamma/beta, first A --
    for (int i = tid; i < 128 * 32; i += 512) {
        int k = i >> 5, q = i & 31;
        float4 w = *(const float4*)&Wl[k * DD + q * 4];
#pragma unroll
        for (int e = 0; e < 4; ++e) {
            int n = q * 4 + e;
            float val = (e == 0) ? w.x : (e == 1) ? w.y : (e == 2) ? w.z : w.w;
            __nv_bfloat16 hi, lo;
            bsplit(val, hi, lo);
            ((__nv_bfloat16*)(smc + SM_BHI))[n * ATS + k] = hi;
            ((__nv_bfloat16*)(smc + SM_BLO))[n * ATS + k] = lo;
        }
    }
    // !FINAL: scale gamma/beta by log2e so h2 = relu(LN)*log2e comes out free
    float pscale = FINAL ? 1.f : L2E;
    for (int i = tid; i < 128; i += 512) {
        ((float*)(smc + SM_BIAS))[i] = bl[i];
        ((float*)(smc + SM_GAM))[i]  = gl[i] * pscale;
        ((float*)(smc + SM_BET))[i]  = btl[i] * pscale;
    }
    // prefetch first A tile into buf0
    {
        int t0 = blockIdx.x;
        if (t0 < NTILES) {
            int row0 = t0 * 128;
            char* dsth = smc + SM_A;
            char* dstl = dsth + 128 * ATS_B;
            for (int i = tid; i < 128 * 16; i += 512) {
                int r = i >> 4, ch = (i & 15) * 16;
                int grow = row0 + r;
                int gz = (grow < NN) ? 0 : 16;
                int gr = (grow < NN) ? grow : 0;
                __pipeline_memcpy_async(dsth + r * ATS_B + ch,
                                        (const char*)(g_Ahi + gr * DD) + ch, 16, gz);
                __pipeline_memcpy_async(dstl + r * ATS_B + ch,
                                        (const char*)(g_Alo + gr * DD) + ch, 16, gz);
            }
        }
    }
    __pipeline_commit();
    __syncthreads();

    // ldmatrix per-lane offsets (proven R9 mappings)
    uint32_t a_loff = (uint32_t)(((lane & 15) * ATS + (lane >> 4) * 8) * 2);
    uint32_t b_loff = (uint32_t)((((lane & 7) + ((lane >> 4) & 1) * 8) * ATS
                                  + ((lane >> 3) & 1) * 8) * 2);
    uint32_t bhi_base = sb + SM_BHI + (uint32_t)(wn * 32 * ATS_B) + b_loff;
    uint32_t blo_base = sb + SM_BLO + (uint32_t)(wn * 32 * ATS_B) + b_loff;

    const float* bias = (const float*)(smc + SM_BIAS);
    const float* gam  = (const float*)(smc + SM_GAM);
    const float* bet  = (const float*)(smc + SM_BET);
    float2* lnp       = (float2*)(smc + SM_LNP);

    int l23 = lane >> 2;
    int lc  = (lane & 3) * 2;

    int buf = 0;
    for (int t = blockIdx.x; t < NTILES; t += gridDim.x) {
        int row0 = t * 128;
        __pipeline_wait_prior(0);
        __syncthreads();

        int tn = t + (int)gridDim.x;
        if (tn < NTILES) {
            int row0n = tn * 128;
            char* dsth = smc + SM_A + (buf ^ 1) * (2 * 128 * ATS_B);
            char* dstl = dsth + 128 * ATS_B;
            for (int i = tid; i < 128 * 16; i += 512) {
                int r = i >> 4, ch = (i & 15) * 16;
                int grow = row0n + r;
                int gz = (grow < NN) ? 0 : 16;
                int gr = (grow < NN) ? grow : 0;
                __pipeline_memcpy_async(dsth + r * ATS_B + ch,
                                        (const char*)(g_Ahi + gr * DD) + ch, 16, gz);
                __pipeline_memcpy_async(dstl + r * ATS_B + ch,
                                        (const char*)(g_Alo + gr * DD) + ch, 16, gz);
            }
        }
        __pipeline_commit();

        uint32_t abase_hi = sb + SM_A + (uint32_t)(buf * 2 * 128 * ATS_B) + a_loff
                          + (uint32_t)(wm * 32 * ATS_B);
        uint32_t abase_lo = abase_hi + (uint32_t)(128 * ATS_B);

        float acc[2][4][4];
#pragma unroll
        for (int mt = 0; mt < 2; ++mt)
#pragma unroll
            for (int nt = 0; nt < 4; ++nt)
#pragma unroll
                for (int e = 0; e < 4; ++e) acc[mt][nt][e] = 0.f;

#pragma unroll
        for (int ks = 0; ks < 8; ++ks) {
            uint32_t kofs = (uint32_t)(ks * 32);
            uint32_t bh00, bh01, bh02, bh03, bh10, bh11, bh12, bh13;
            uint32_t bl00, bl01, bl02, bl03, bl10, bl11, bl12, bl13;
            ldsm4(bh00, bh01, bh02, bh03, bhi_base + kofs);
            ldsm4(bh10, bh11, bh12, bh13, bhi_base + 16 * ATS_B + kofs);
            ldsm4(bl00, bl01, bl02, bl03, blo_base + kofs);
            ldsm4(bl10, bl11, bl12, bl13, blo_base + 16 * ATS_B + kofs);
#pragma unroll
            for (int mt = 0; mt < 2; ++mt) {
                uint32_t arow = (uint32_t)(mt * 16 * ATS_B) + kofs;
                uint32_t ah0, ah1, ah2, ah3, al0, al1, al2, al3;
                ldsm4(ah0, ah1, ah2, ah3, abase_hi + arow);
                ldsm4(al0, al1, al2, al3, abase_lo + arow);
                mma_bf16(acc[mt][0][0], acc[mt][0][1], acc[mt][0][2], acc[mt][0][3],
                         ah0, ah1, ah2, ah3, bh00, bh01);
                mma_bf16(acc[mt][0][0], acc[mt][0][1], acc[mt][0][2], acc[mt][0][3],
                         ah0, ah1, ah2, ah3, bl00, bl01);
                mma_bf16(acc[mt][0][0], acc[mt][0][1], acc[mt][0][2], acc[mt][0][3],
                         al0, al1, al2, al3, bh00, bh01);
                mma_bf16(acc[mt][1][0], acc[mt][1][1], acc[mt][1][2], acc[mt][1][3],
                         ah0, ah1, ah2, ah3, bh02, bh03);
                mma_bf16(acc[mt][1][0], acc[mt][1][1], acc[mt][1][2], acc[mt][1][3],
                         ah0, ah1, ah2, ah3, bl02, bl03);
                mma_bf16(acc[mt][1][0], acc[mt][1][1], acc[mt][1][2], acc[mt][1][3],
                         al0, al1, al2, al3, bh02, bh03);
                mma_bf16(acc[mt][2][0], acc[mt][2][1], acc[mt][2][2], acc[mt][2][3],
                         ah0, ah1, ah2, ah3, bh10, bh11);
                mma_bf16(acc[mt][2][0], acc[mt][2][1], acc[mt][2][2], acc[mt][2][3],
                         ah0, ah1, ah2, ah3, bl10, bl11);
                mma_bf16(acc[mt][2][0], acc[mt][2][1], acc[mt][2][2], acc[mt][2][3],
                         al0, al1, al2, al3, bh10, bh11);
                mma_bf16(acc[mt][3][0], acc[mt][3][1], acc[mt][3][2], acc[mt][3][3],
                         ah0, ah1, ah2, ah3, bh12, bh13);
                mma_bf16(acc[mt][3][0], acc[mt][3][1], acc[mt][3][2], acc[mt][3][3],
                         ah0, ah1, ah2, ah3, bl12, bl13);
                mma_bf16(acc[mt][3][0], acc[mt][3][1], acc[mt][3][2], acc[mt][3][3],
                         al0, al1, al2, al3, bh12, bh13);
            }
        }

        // ---- epilogue: bias (+residual), LN partials, normalize, store ----
#pragma unroll
        for (int mt = 0; mt < 2; ++mt) {
            int rl0 = wm * 32 + mt * 16 + l23;
            int rl1 = rl0 + 8;
            int gr0 = row0 + rl0, gr1 = row0 + rl1;
            int gc0 = (gr0 < NN) ? gr0 : 0;
            int gc1 = (gr1 < NN) ? gr1 : 0;
            float s0 = 0.f, q0 = 0.f, s1 = 0.f, q1 = 0.f;
#pragma unroll
            for (int nt = 0; nt < 4; ++nt) {
                int c = wn * 32 + nt * 8 + lc;
                float2 bv = *(const float2*)(bias + c);
                float v0 = acc[mt][nt][0] + bv.x;
                float v1 = acc[mt][nt][1] + bv.y;
                float v2 = acc[mt][nt][2] + bv.x;
                float v3 = acc[mt][nt][3] + bv.y;
                if (RES) {
                    float2 r0 = *(const float2*)&g_h[gc0 * DD + c];
                    float2 r1 = *(const float2*)&g_h[gc1 * DD + c];
                    v0 += r0.x; v1 += r0.y; v2 += r1.x; v3 += r1.y;
                }
                acc[mt][nt][0] = v0; acc[mt][nt][1] = v1;
                acc[mt][nt][2] = v2; acc[mt][nt][3] = v3;
                s0 += v0 + v1; q0 += v0 * v0 + v1 * v1;
                s1 += v2 + v3; q1 += v2 * v2 + v3 * v3;
            }
            s0 += __shfl_xor_sync(0xffffffffu, s0, 1); s0 += __shfl_xor_sync(0xffffffffu, s0, 2);
            q0 += __shfl_xor_sync(0xffffffffu, q0, 1); q0 += __shfl_xor_sync(0xffffffffu, q0, 2);
            s1 += __shfl_xor_sync(0xffffffffu, s1, 1); s1 += __shfl_xor_sync(0xffffffffu, s1, 2);
            q1 += __shfl_xor_sync(0xffffffffu, q1, 1); q1 += __shfl_xor_sync(0xffffffffu, q1, 2);
            if ((lane & 3) == 0) {
                lnp[rl0 * 4 + wn] = make_float2(s0, q0);
                lnp[rl1 * 4 + wn] = make_float2(s1, q1);
            }
        }
        __syncthreads();

#pragma unroll
        for (int mt = 0; mt < 2; ++mt) {
            int rl0 = wm * 32 + mt * 16 + l23;
            int rl1 = rl0 + 8;
            int gr0 = row0 + rl0, gr1 = row0 + rl1;
            float S0 = 0.f, Q0 = 0.f, S1 = 0.f, Q1 = 0.f;
#pragma unroll
            for (int w = 0; w < 4; ++w) {
                float2 p0 = lnp[rl0 * 4 + w]; S0 += p0.x; Q0 += p0.y;
                float2 p1 = lnp[rl1 * 4 + w]; S1 += p1.x; Q1 += p1.y;
            }
            float mu0 = S0 * (1.f / 128.f), mu1 = S1 * (1.f / 128.f);
            float rs0 = rsqrtf(Q0 * (1.f / 128.f) - mu0 * mu0 + 1e-5f);
            float rs1 = rsqrtf(Q1 * (1.f / 128.f) - mu1 * mu1 + 1e-5f);
#pragma unroll
            for (int nt = 0; nt < 4; ++nt) {
                int c = wn * 32 + nt * 8 + lc;
                float2 gv = *(const float2*)(gam + c);
                float2 tv = *(const float2*)(bet + c);
                float v0 = acc[mt][nt][0], v1 = acc[mt][nt][1];
                float v2 = acc[mt][nt][2], v3 = acc[mt][nt][3];
                float y0 = (v0 - mu0) * rs0 * gv.x + tv.x;
                float y1 = (v1 - mu0) * rs0 * gv.y + tv.y;
                float y2 = (v2 - mu1) * rs1 * gv.x + tv.x;
                float y3 = (v3 - mu1) * rs1 * gv.y + tv.y;
                if (gr0 < NN) {
                    if (FINAL) {
                        *(float2*)&dout[gr0 * DD + c] = make_float2(y0, y1);
                    } else {
                        *(float2*)&g_h [gr0 * DD + c] = make_float2(v0, v1);
                        *(float2*)&g_h2[gr0 * DD + c] = make_float2(fmaxf(y0, 0.f), fmaxf(y1, 0.f));
                    }
                }
                if (gr1 < NN) {
                    if (FINAL) {
                        *(float2*)&dout[gr1 * DD + c] = make_float2(y2, y3);
                    } else {
                        *(float2*)&g_h [gr1 * DD + c] = make_float2(v2, v3);
                        *(float2*)&g_h2[gr1 * DD + c] = make_float2(fmaxf(y2, 0.f), fmaxf(y3, 0.f));
                    }
                }
            }
        }
        buf ^= 1;
        __syncthreads();
    }
}

// ================= launch =====================================================
extern "C" void kernel_launch(void* const* d_in, const int* in_sizes, int n_in,
                              void* d_out, int out_size) {
    const int*   x    = (const int*)  d_in[0];
    const int*   ei   = (const int*)  d_in[1];
    const int*   ea   = (const int*)  d_in[2];
    const float* aemb = (const float*)d_in[3];
    const float* bemb = (const float*)d_in[4];
    const float* W    = (const float*)d_in[5];
    const float* b    = (const float*)d_in[6];
    const float* g    = (const float*)d_in[7];
    const float* bt   = (const float*)d_in[8];
    float* out = (float*)d_out;
    const int* src = ei;
    const int* dst = ei + EE;

    static float *p_hs = nullptr, *p_h2 = nullptr;
    static int sms = 148;
    if (!p_hs) {
        cudaGetSymbolAddress((void**)&p_hs, g_hs);
        cudaGetSymbolAddress((void**)&p_h2, g_h2);
        cudaDeviceGetAttribute(&sms, cudaDevAttrMultiProcessorCount, 0);
        cudaFuncSetAttribute((const void*)k_mma<false, false>, cudaFuncAttributeMaxDynamicSharedMemorySize, SM_TOTAL);
        cudaFuncSetAttribute((const void*)k_mma<true,  false>, cudaFuncAttributeMaxDynamicSharedMemorySize, SM_TOTAL);
        cudaFuncSetAttribute((const void*)k_mma<true,  true >, cudaFuncAttributeMaxDynamicSharedMemorySize, SM_TOTAL);
    }

    k_atom<<<(NN * 32 + 255) / 256, 256>>>(x, aemb, bemb);     // launch 0
    k_scatter<<<(EE + 255) / 256, 256>>>(src, dst, ea);        // launch 1

    int agg_blocks = sms * 5;
    for (int l = 0; l < 7; ++l) {
        const float* Wl  = W  + l * DD * DD;
        const float* bl  = b  + l * DD;
        const float* gl  = g  + l * DD;
        const float* btl = bt + l * DD;
        const float* hi = (l == 0) ? p_hs : p_h2;
        k_agg<<<agg_blocks, 256>>>(hi);                        // launch 2 = agg0
        if (l == 0)
            k_mma<false, false><<<sms, 512, SM_TOTAL>>>(Wl, bl, gl, btl, out);  // launch 3 (profiled)
        else if (l < 6)
            k_mma<true, false><<<sms, 512, SM_TOTAL>>>(Wl, bl, gl, btl, out);
        else
            k_mma<true, true><<<sms, 512, SM_TOTAL>>>(Wl, bl, gl, btl, out);
    }
}